// round 3
// baseline (speedup 1.0000x reference)
#include <cuda_runtime.h>

#define NMAX 100000
#define EMAX 1600000
#define D 128

// ---- scratch (no allocations allowed -> __device__ globals) ----
__device__ int   g_deg[NMAX];
__device__ float g_dinv[NMAX];
__device__ int   g_colptr[NMAX + 1];
__device__ int   g_cursor[NMAX];
__device__ int   g_srow[EMAX];
__device__ float g_h[(size_t)NMAX * D];   // GEMM output / layer features
__device__ float g_z[(size_t)NMAX * D];   // relu(layer1) output
__device__ int   g_part[256];             // scan partials

// ---------------- degree + dinv ----------------
__global__ void k_deg_init(int n) {
    int i = blockIdx.x * blockDim.x + threadIdx.x;
    if (i < n) g_deg[i] = 0;
}

__global__ void k_deg_count(const int* __restrict__ col, int e) {
    int i = blockIdx.x * blockDim.x + threadIdx.x;
    if (i < e) atomicAdd(&g_deg[col[i]], 1);
}

__global__ void k_dinv(int n) {
    int i = blockIdx.x * blockDim.x + threadIdx.x;
    if (i < n) g_dinv[i] = rsqrtf((float)(g_deg[i] + 1));
}

// ---------------- exclusive scan of g_deg -> g_colptr ----------------
#define SCAN_T 256
#define SCAN_I 8
#define SCAN_C (SCAN_T * SCAN_I)   // 2048 elements per block

__global__ void k_scan_partial(int n) {
    __shared__ int ss[SCAN_T];
    int b = blockIdx.x, tid = threadIdx.x;
    int base = b * SCAN_C + tid * SCAN_I;
    int s = 0;
    #pragma unroll
    for (int i = 0; i < SCAN_I; i++) {
        int idx = base + i;
        if (idx < n) s += g_deg[idx];
    }
    ss[tid] = s;
    __syncthreads();
    for (int off = SCAN_T / 2; off > 0; off >>= 1) {
        if (tid < off) ss[tid] += ss[tid + off];
        __syncthreads();
    }
    if (tid == 0) g_part[b] = ss[0];
}

__global__ void k_scan_offsets(int nb) {
    if (threadIdx.x == 0) {
        int run = 0;
        for (int i = 0; i < nb; i++) {
            int v = g_part[i];
            g_part[i] = run;
            run += v;
        }
    }
}

__global__ void k_scan_final(int n, int e) {
    __shared__ int ss[SCAN_T];
    int b = blockIdx.x, tid = threadIdx.x;
    int base = b * SCAN_C + tid * SCAN_I;
    int vals[SCAN_I];
    int local = 0;
    #pragma unroll
    for (int i = 0; i < SCAN_I; i++) {
        int idx = base + i;
        int v = (idx < n) ? g_deg[idx] : 0;
        vals[i] = local;    // exclusive within thread
        local += v;
    }
    ss[tid] = local;
    __syncthreads();
    // Hillis-Steele inclusive scan over thread totals
    for (int off = 1; off < SCAN_T; off <<= 1) {
        int v = 0;
        if (tid >= off) v = ss[tid - off];
        __syncthreads();
        ss[tid] += v;
        __syncthreads();
    }
    int toff = g_part[b] + ss[tid] - local;   // exclusive offset for this thread
    #pragma unroll
    for (int i = 0; i < SCAN_I; i++) {
        int idx = base + i;
        if (idx < n) {
            int p = toff + vals[i];
            g_colptr[idx] = p;
            g_cursor[idx] = p;
        }
    }
    if (b == 0 && tid == 0) g_colptr[n] = e;
}

// ---------------- CSR fill (counting sort by destination) ----------------
__global__ void k_fill(const int* __restrict__ row, const int* __restrict__ col, int e) {
    int i = blockIdx.x * blockDim.x + threadIdx.x;
    if (i < e) {
        int p = atomicAdd(&g_cursor[col[i]], 1);
        g_srow[p] = row[i];
    }
}

// ---------------- GEMM: C[n,128] = A[n,128] @ W[128,128] ----------------
// BM=128, BN=128, BK=32; 256 threads; each thread: 2x2 quads of 4x4 (8x8 outputs)
__global__ void __launch_bounds__(256) k_gemm(const float* __restrict__ A,
                                              const float* __restrict__ W,
                                              float* __restrict__ C, int n) {
    __shared__ float As[32][132];   // [k][m], padded (132*4 = 528 B, 16B-aligned rows)
    __shared__ float Bs[32][128];   // [k][n]

    int tid = threadIdx.x;
    int tx = tid & 15;     // 16 col groups
    int ty = tid >> 4;     // 16 row groups
    int row0 = blockIdx.x * 128;

    float acc[2][2][4][4];
    #pragma unroll
    for (int a = 0; a < 2; a++)
        #pragma unroll
        for (int b = 0; b < 2; b++)
            #pragma unroll
            for (int i = 0; i < 4; i++)
                #pragma unroll
                for (int j = 0; j < 4; j++)
                    acc[a][b][i][j] = 0.0f;

    for (int k0 = 0; k0 < D; k0 += 32) {
        // load A tile 128x32 (transposed into As[k][m])
        #pragma unroll
        for (int l = 0; l < 4; l++) {
            int t = tid + l * 256;       // 0..1023 float4 slots
            int m  = t >> 3;             // row in tile
            int kq = t & 7;              // float4 index along k
            float4 v = make_float4(0.f, 0.f, 0.f, 0.f);
            int gm = row0 + m;
            if (gm < n) v = *(const float4*)(A + (size_t)gm * D + k0 + kq * 4);
            As[kq * 4 + 0][m] = v.x;
            As[kq * 4 + 1][m] = v.y;
            As[kq * 4 + 2][m] = v.z;
            As[kq * 4 + 3][m] = v.w;
        }
        // load W tile 32x128
        #pragma unroll
        for (int l = 0; l < 4; l++) {
            int t = tid + l * 256;
            int kk = t >> 5;
            int nq = t & 31;
            *(float4*)&Bs[kk][nq * 4] = *(const float4*)(W + (size_t)(k0 + kk) * D + nq * 4);
        }
        __syncthreads();

        #pragma unroll 4
        for (int kk = 0; kk < 32; kk++) {
            float4 a0 = *(float4*)&As[kk][ty * 4];
            float4 a1 = *(float4*)&As[kk][ty * 4 + 64];
            float4 b0 = *(float4*)&Bs[kk][tx * 4];
            float4 b1 = *(float4*)&Bs[kk][tx * 4 + 64];
            float av[2][4] = {{a0.x, a0.y, a0.z, a0.w}, {a1.x, a1.y, a1.z, a1.w}};
            float bv[2][4] = {{b0.x, b0.y, b0.z, b0.w}, {b1.x, b1.y, b1.z, b1.w}};
            #pragma unroll
            for (int r2 = 0; r2 < 2; r2++)
                #pragma unroll
                for (int c2 = 0; c2 < 2; c2++)
                    #pragma unroll
                    for (int i = 0; i < 4; i++)
                        #pragma unroll
                        for (int j = 0; j < 4; j++)
                            acc[r2][c2][i][j] += av[r2][i] * bv[c2][j];
        }
        __syncthreads();
    }

    #pragma unroll
    for (int r2 = 0; r2 < 2; r2++)
        #pragma unroll
        for (int i = 0; i < 4; i++) {
            int gm = row0 + ty * 4 + r2 * 64 + i;
            if (gm < n) {
                #pragma unroll
                for (int c2 = 0; c2 < 2; c2++) {
                    float4 v = make_float4(acc[r2][c2][i][0], acc[r2][c2][i][1],
                                           acc[r2][c2][i][2], acc[r2][c2][i][3]);
                    *(float4*)(C + (size_t)gm * D + tx * 4 + c2 * 64) = v;
                }
            }
        }
}

// ---------------- aggregation: out[c] = sum_{e:col=c} dinv[r]*dinv[c]*h[r] + dinv[c]^2*h[c] (+bias, relu) ----------------
// one warp per node, float4 per lane -> 512B coalesced per feature row
__global__ void k_agg(const float* __restrict__ h, const float* __restrict__ bias,
                      float* __restrict__ out, int n, int do_relu) {
    int gt = blockIdx.x * blockDim.x + threadIdx.x;
    int c = gt >> 5;
    int lane = gt & 31;
    if (c >= n) return;

    float dc = g_dinv[c];
    const float4* h4 = (const float4*)h;
    float4 v = h4[(size_t)c * 32 + lane];
    float s = dc * dc;
    float ax = v.x * s, ay = v.y * s, az = v.z * s, aw = v.w * s;

    int i = g_colptr[c];
    int end = g_colptr[c + 1];
    // software-pipeline the srow load to hide L2 latency in the chain
    int r_next = (i < end) ? g_srow[i] : 0;
    while (i < end) {
        int r = r_next;
        int j = i + 1;
        if (j < end) r_next = g_srow[j];
        float w = g_dinv[r] * dc;
        float4 u = h4[(size_t)r * 32 + lane];
        ax += w * u.x;
        ay += w * u.y;
        az += w * u.z;
        aw += w * u.w;
        i = j;
    }

    float4 bv = ((const float4*)bias)[lane];
    ax += bv.x; ay += bv.y; az += bv.z; aw += bv.w;
    if (do_relu) {
        ax = fmaxf(ax, 0.f); ay = fmaxf(ay, 0.f);
        az = fmaxf(az, 0.f); aw = fmaxf(aw, 0.f);
    }
    ((float4*)out)[(size_t)c * 32 + lane] = make_float4(ax, ay, az, aw);
}

// ---------------- launch ----------------
extern "C" void kernel_launch(void* const* d_in, const int* in_sizes, int n_in,
                              void* d_out, int out_size) {
    const float* x  = (const float*)d_in[0];
    const int*   ei = (const int*)d_in[1];
    const float* W1 = (const float*)d_in[2];
    const float* b1 = (const float*)d_in[3];
    const float* W2 = (const float*)d_in[4];
    const float* b2 = (const float*)d_in[5];
    float* out = (float*)d_out;

    int n = in_sizes[0] / D;
    int e = in_sizes[1] / 2;
    const int* row = ei;
    const int* col = ei + e;

    void *ph = nullptr, *pz = nullptr;
    cudaGetSymbolAddress(&ph, g_h);
    cudaGetSymbolAddress(&pz, g_z);
    float* h = (float*)ph;
    float* z = (float*)pz;

    int nb = (n + SCAN_C - 1) / SCAN_C;

    k_deg_init<<<(n + 255) / 256, 256>>>(n);
    k_deg_count<<<(e + 255) / 256, 256>>>(col, e);
    k_dinv<<<(n + 255) / 256, 256>>>(n);
    k_scan_partial<<<nb, SCAN_T>>>(n);
    k_scan_offsets<<<1, 32>>>(nb);
    k_scan_final<<<nb, SCAN_T>>>(n, e);
    k_fill<<<(e + 255) / 256, 256>>>(row, col, e);

    int gemm_blocks = (n + 127) / 128;
    int agg_blocks = (n * 32 + 255) / 256;

    // layer 1: h = x @ W1 ; z = relu(Ahat h + b1)
    k_gemm<<<gemm_blocks, 256>>>(x, W1, h, n);
    k_agg<<<agg_blocks, 256>>>(h, b1, z, n, 1);
    // layer 2: h = z @ W2 ; out = Ahat h + b2
    k_gemm<<<gemm_blocks, 256>>>(z, W2, h, n);
    k_agg<<<agg_blocks, 256>>>(h, b2, out, n, 0);
}

// round 5
// speedup vs baseline: 1.3166x; 1.3166x over previous
#include <cuda_runtime.h>
#include <cstdint>

#define NMAX 100000
#define EMAX 1600000
#define D 128

// ---- scratch (no allocations allowed -> __device__ globals) ----
__device__ int   g_deg[NMAX];
__device__ float g_dinv[NMAX];
__device__ int   g_colptr[NMAX + 1];
__device__ int   g_cursor[NMAX];
__device__ int   g_srow[EMAX];
__device__ float g_h[(size_t)NMAX * D];   // GEMM output / layer features
__device__ float g_z[(size_t)NMAX * D];   // relu(layer1) output
__device__ int   g_part[256];             // scan partials

__device__ __forceinline__ float to_tf32(float x) {
    float y;
    asm("cvt.rna.tf32.f32 %0, %1;" : "=f"(y) : "f"(x));
    return y;
}

// ---------------- degree + dinv ----------------
__global__ void k_deg_init(int n) {
    int i = blockIdx.x * blockDim.x + threadIdx.x;
    if (i < n) g_deg[i] = 0;
}
__global__ void k_deg_count(const int* __restrict__ col, int e) {
    int i = blockIdx.x * blockDim.x + threadIdx.x;
    if (i < e) atomicAdd(&g_deg[col[i]], 1);
}
__global__ void k_dinv(int n) {
    int i = blockIdx.x * blockDim.x + threadIdx.x;
    if (i < n) g_dinv[i] = rsqrtf((float)(g_deg[i] + 1));
}

// ---------------- exclusive scan of g_deg -> g_colptr ----------------
#define SCAN_T 256
#define SCAN_I 8
#define SCAN_C (SCAN_T * SCAN_I)

__global__ void k_scan_partial(int n) {
    __shared__ int ss[SCAN_T];
    int b = blockIdx.x, tid = threadIdx.x;
    int base = b * SCAN_C + tid * SCAN_I;
    int s = 0;
    #pragma unroll
    for (int i = 0; i < SCAN_I; i++) {
        int idx = base + i;
        if (idx < n) s += g_deg[idx];
    }
    ss[tid] = s;
    __syncthreads();
    for (int off = SCAN_T / 2; off > 0; off >>= 1) {
        if (tid < off) ss[tid] += ss[tid + off];
        __syncthreads();
    }
    if (tid == 0) g_part[b] = ss[0];
}

__global__ void k_scan_offsets(int nb) {
    if (threadIdx.x == 0) {
        int run = 0;
        for (int i = 0; i < nb; i++) {
            int v = g_part[i];
            g_part[i] = run;
            run += v;
        }
    }
}

__global__ void k_scan_final(int n, int e) {
    __shared__ int ss[SCAN_T];
    int b = blockIdx.x, tid = threadIdx.x;
    int base = b * SCAN_C + tid * SCAN_I;
    int vals[SCAN_I];
    int local = 0;
    #pragma unroll
    for (int i = 0; i < SCAN_I; i++) {
        int idx = base + i;
        int v = (idx < n) ? g_deg[idx] : 0;
        vals[i] = local;
        local += v;
    }
    ss[tid] = local;
    __syncthreads();
    for (int off = 1; off < SCAN_T; off <<= 1) {
        int v = 0;
        if (tid >= off) v = ss[tid - off];
        __syncthreads();
        ss[tid] += v;
        __syncthreads();
    }
    int toff = g_part[b] + ss[tid] - local;
    #pragma unroll
    for (int i = 0; i < SCAN_I; i++) {
        int idx = base + i;
        if (idx < n) {
            int p = toff + vals[i];
            g_colptr[idx] = p;
            g_cursor[idx] = p;
        }
    }
    if (b == 0 && tid == 0) g_colptr[n] = e;
}

// ---------------- CSR fill ----------------
__global__ void k_fill(const int* __restrict__ row, const int* __restrict__ col, int e) {
    int i = blockIdx.x * blockDim.x + threadIdx.x;
    if (i < e) {
        int p = atomicAdd(&g_cursor[col[i]], 1);
        g_srow[p] = row[i];
    }
}

// ---------------- tf32 mma.sync GEMM: C[n,128] = A[n,128] @ W[128,128] ----------------
// CTA tile 128x128, full K=128 in smem. 8 warps (2 M x 4 N), warp tile 64x32.
// A smem stride 132 (bank = 4g+c distinct), B smem stride 136 (bank = 8c+g distinct).
#define AST 132
#define BST 136
#define GSMEM_FLOATS (128 * AST + 128 * BST)   // 34304 floats = 137216 B

#define MMA_TF32(d, a, b) \
    asm volatile("mma.sync.aligned.m16n8k8.row.col.f32.tf32.tf32.f32 " \
        "{%0,%1,%2,%3}, {%4,%5,%6,%7}, {%8,%9}, {%0,%1,%2,%3};" \
        : "+f"((d)[0]), "+f"((d)[1]), "+f"((d)[2]), "+f"((d)[3]) \
        : "r"((a)[0]), "r"((a)[1]), "r"((a)[2]), "r"((a)[3]), \
          "r"((b)[0]), "r"((b)[1]))

__global__ void __launch_bounds__(256) k_gemm_mma(const float* __restrict__ A,
                                                  const float* __restrict__ W,
                                                  float* __restrict__ C, int n) {
    extern __shared__ float smem[];
    float* As = smem;               // [128][AST]
    float* Bs = smem + 128 * AST;   // [128][BST]

    int tid = threadIdx.x;
    int wid = tid >> 5, lane = tid & 31;
    int gq = lane >> 2;    // groupID 0..7
    int cq = lane & 3;     // threadID_in_group 0..3
    int row0 = blockIdx.x << 7;

    // fill A tile (tf32-rounded)
    #pragma unroll
    for (int it = 0; it < 16; it++) {
        int t = tid + it * 256;     // float4 slot 0..4095
        int m = t >> 5, kq = t & 31;
        int gm = row0 + m;
        float4 v = make_float4(0.f, 0.f, 0.f, 0.f);
        if (gm < n) v = *(const float4*)(A + (size_t)gm * D + kq * 4);
        v.x = to_tf32(v.x); v.y = to_tf32(v.y);
        v.z = to_tf32(v.z); v.w = to_tf32(v.w);
        *(float4*)(As + m * AST + kq * 4) = v;
    }
    // fill B tile: Bs[k][nn] = tf32(W[k][nn])
    #pragma unroll
    for (int it = 0; it < 16; it++) {
        int t = tid + it * 256;
        int k = t >> 5, nq = t & 31;
        float4 v = *(const float4*)(W + (size_t)k * D + nq * 4);
        v.x = to_tf32(v.x); v.y = to_tf32(v.y);
        v.z = to_tf32(v.z); v.w = to_tf32(v.w);
        *(float4*)(Bs + k * BST + nq * 4) = v;
    }
    __syncthreads();

    int wm = (wid >> 2) << 6;    // 0 or 64
    int wn = (wid & 3) << 5;     // 0,32,64,96

    float acc[4][4][4];
    #pragma unroll
    for (int mt = 0; mt < 4; mt++)
        #pragma unroll
        for (int nt = 0; nt < 4; nt++)
            #pragma unroll
            for (int i = 0; i < 4; i++)
                acc[mt][nt][i] = 0.f;

    const uint32_t* Au = (const uint32_t*)As;
    const uint32_t* Bu = (const uint32_t*)Bs;

    #pragma unroll 4
    for (int kt = 0; kt < 16; kt++) {
        int k0 = kt << 3;
        uint32_t a[4][4];
        uint32_t b[4][2];
        #pragma unroll
        for (int mt = 0; mt < 4; mt++) {
            const uint32_t* ap = Au + (wm + (mt << 4)) * AST + k0;
            a[mt][0] = ap[gq * AST + cq];
            a[mt][1] = ap[(gq + 8) * AST + cq];
            a[mt][2] = ap[gq * AST + cq + 4];
            a[mt][3] = ap[(gq + 8) * AST + cq + 4];
        }
        #pragma unroll
        for (int nt = 0; nt < 4; nt++) {
            const uint32_t* bp = Bu + k0 * BST + wn + (nt << 3);
            b[nt][0] = bp[cq * BST + gq];
            b[nt][1] = bp[(cq + 4) * BST + gq];
        }
        #pragma unroll
        for (int mt = 0; mt < 4; mt++)
            #pragma unroll
            for (int nt = 0; nt < 4; nt++)
                MMA_TF32(acc[mt][nt], a[mt], b[nt]);
    }

    // store C: c0,c1 at (row gq, cols 2cq,2cq+1), c2,c3 at row gq+8
    #pragma unroll
    for (int mt = 0; mt < 4; mt++) {
        int r0 = row0 + wm + (mt << 4) + gq;
        int r1 = r0 + 8;
        #pragma unroll
        for (int nt = 0; nt < 4; nt++) {
            int cc = wn + (nt << 3) + (cq << 1);
            if (r0 < n)
                *(float2*)(C + (size_t)r0 * D + cc) =
                    make_float2(acc[mt][nt][0], acc[mt][nt][1]);
            if (r1 < n)
                *(float2*)(C + (size_t)r1 * D + cc) =
                    make_float2(acc[mt][nt][2], acc[mt][nt][3]);
        }
    }
}

// ---------------- aggregation ----------------
__global__ void k_agg(const float* __restrict__ h, const float* __restrict__ bias,
                      float* __restrict__ out, int n, int do_relu) {
    int gt = blockIdx.x * blockDim.x + threadIdx.x;
    int c = gt >> 5;
    int lane = gt & 31;
    if (c >= n) return;

    float dc = g_dinv[c];
    const float4* h4 = (const float4*)h;
    float4 v = h4[(size_t)c * 32 + lane];
    float s = dc * dc;
    float ax = v.x * s, ay = v.y * s, az = v.z * s, aw = v.w * s;

    int i = g_colptr[c];
    int end = g_colptr[c + 1];
    int r_next = (i < end) ? g_srow[i] : 0;
    while (i < end) {
        int r = r_next;
        int j = i + 1;
        if (j < end) r_next = g_srow[j];
        float w = g_dinv[r] * dc;
        float4 u = h4[(size_t)r * 32 + lane];
        ax += w * u.x;
        ay += w * u.y;
        az += w * u.z;
        aw += w * u.w;
        i = j;
    }

    float4 bv = ((const float4*)bias)[lane];
    ax += bv.x; ay += bv.y; az += bv.z; aw += bv.w;
    if (do_relu) {
        ax = fmaxf(ax, 0.f); ay = fmaxf(ay, 0.f);
        az = fmaxf(az, 0.f); aw = fmaxf(aw, 0.f);
    }
    ((float4*)out)[(size_t)c * 32 + lane] = make_float4(ax, ay, az, aw);
}

// ---------------- launch ----------------
extern "C" void kernel_launch(void* const* d_in, const int* in_sizes, int n_in,
                              void* d_out, int out_size) {
    const float* x  = (const float*)d_in[0];
    const int*   ei = (const int*)d_in[1];
    const float* W1 = (const float*)d_in[2];
    const float* b1 = (const float*)d_in[3];
    const float* W2 = (const float*)d_in[4];
    const float* b2 = (const float*)d_in[5];
    float* out = (float*)d_out;

    int n = in_sizes[0] / D;
    int e = in_sizes[1] / 2;
    const int* row = ei;
    const int* col = ei + e;

    void *ph = nullptr, *pz = nullptr;
    cudaGetSymbolAddress(&ph, g_h);
    cudaGetSymbolAddress(&pz, g_z);
    float* h = (float*)ph;
    float* z = (float*)pz;

    static int smem_set = 0;
    if (!smem_set) {
        cudaFuncSetAttribute(k_gemm_mma, cudaFuncAttributeMaxDynamicSharedMemorySize,
                             GSMEM_FLOATS * 4);
        smem_set = 1;
    }

    int nb = (n + SCAN_C - 1) / SCAN_C;

    k_deg_init<<<(n + 255) / 256, 256>>>(n);
    k_deg_count<<<(e + 255) / 256, 256>>>(col, e);
    k_dinv<<<(n + 255) / 256, 256>>>(n);
    k_scan_partial<<<nb, SCAN_T>>>(n);
    k_scan_offsets<<<1, 32>>>(nb);
    k_scan_final<<<nb, SCAN_T>>>(n, e);
    k_fill<<<(e + 255) / 256, 256>>>(row, col, e);

    int gemm_blocks = (n + 127) / 128;
    int agg_blocks = (n * 32 + 255) / 256;

    // layer 1: h = x @ W1 ; z = relu(Ahat h + b1)
    k_gemm_mma<<<gemm_blocks, 256, GSMEM_FLOATS * 4>>>(x, W1, h, n);
    k_agg<<<agg_blocks, 256>>>(h, b1, z, n, 1);
    // layer 2: h = z @ W2 ; out = Ahat h + b2
    k_gemm_mma<<<gemm_blocks, 256, GSMEM_FLOATS * 4>>>(z, W2, h, n);
    k_agg<<<agg_blocks, 256>>>(h, b2, out, n, 0);
}

// round 6
// speedup vs baseline: 1.4104x; 1.0712x over previous
#include <cuda_runtime.h>
#include <cstdint>

#define NMAX 100000
#define EMAX 1600000
#define D 128

// ---- scratch (no allocations allowed -> __device__ globals) ----
__device__ int   g_deg[NMAX];
__device__ float g_dinv[NMAX];
__device__ int   g_colptr[NMAX + 1];
__device__ int   g_cursor[NMAX];
__device__ int   g_srow[EMAX];
__device__ float g_h[(size_t)NMAX * D];
__device__ float g_z[(size_t)NMAX * D];
__device__ int   g_part[256];

__device__ __forceinline__ float to_tf32(float x) {
    float y;
    asm("cvt.rna.tf32.f32 %0, %1;" : "=f"(y) : "f"(x));
    return y;
}

// ---------------- degree ----------------
__global__ void k_deg_init(int n) {
    int i = blockIdx.x * blockDim.x + threadIdx.x;
    if (i < n) g_deg[i] = 0;
}
__global__ void k_deg_count(const int* __restrict__ col, int e) {
    int i = blockIdx.x * blockDim.x + threadIdx.x;
    if (i < e) atomicAdd(&g_deg[col[i]], 1);
}

// ---------------- exclusive scan of g_deg -> g_colptr (+dinv fused) ----------------
#define SCAN_T 256
#define SCAN_I 8
#define SCAN_C (SCAN_T * SCAN_I)

__global__ void k_scan_partial(int n) {
    __shared__ int ss[SCAN_T];
    int b = blockIdx.x, tid = threadIdx.x;
    int base = b * SCAN_C + tid * SCAN_I;
    int s = 0;
    #pragma unroll
    for (int i = 0; i < SCAN_I; i++) {
        int idx = base + i;
        if (idx < n) s += g_deg[idx];
    }
    ss[tid] = s;
    __syncthreads();
    for (int off = SCAN_T / 2; off > 0; off >>= 1) {
        if (tid < off) ss[tid] += ss[tid + off];
        __syncthreads();
    }
    if (tid == 0) g_part[b] = ss[0];
}

__global__ void k_scan_offsets(int nb) {
    if (threadIdx.x == 0) {
        int run = 0;
        for (int i = 0; i < nb; i++) {
            int v = g_part[i];
            g_part[i] = run;
            run += v;
        }
    }
}

__global__ void k_scan_final(int n, int e) {
    __shared__ int ss[SCAN_T];
    int b = blockIdx.x, tid = threadIdx.x;
    int base = b * SCAN_C + tid * SCAN_I;
    int vals[SCAN_I];
    int degs[SCAN_I];
    int local = 0;
    #pragma unroll
    for (int i = 0; i < SCAN_I; i++) {
        int idx = base + i;
        int v = (idx < n) ? g_deg[idx] : 0;
        degs[i] = v;
        vals[i] = local;
        local += v;
    }
    ss[tid] = local;
    __syncthreads();
    for (int off = 1; off < SCAN_T; off <<= 1) {
        int v = 0;
        if (tid >= off) v = ss[tid - off];
        __syncthreads();
        ss[tid] += v;
        __syncthreads();
    }
    int toff = g_part[b] + ss[tid] - local;
    #pragma unroll
    for (int i = 0; i < SCAN_I; i++) {
        int idx = base + i;
        if (idx < n) {
            int p = toff + vals[i];
            g_colptr[idx] = p;
            g_cursor[idx] = p;
            g_dinv[idx] = rsqrtf((float)(degs[i] + 1));   // fused dinv
        }
    }
    if (b == 0 && tid == 0) g_colptr[n] = e;
}

// ---------------- CSR fill ----------------
__global__ void k_fill(const int* __restrict__ row, const int* __restrict__ col, int e) {
    int i = blockIdx.x * blockDim.x + threadIdx.x;
    if (i < e) {
        int p = atomicAdd(&g_cursor[col[i]], 1);
        g_srow[p] = row[i];
    }
}

// ---------------- tf32 mma.sync GEMM: C[n,128] = A[n,128] @ W[128,128] ----------------
// CTA tile 128x128, K split into 2 chunks of 64 -> 70KB smem -> 2 CTAs/SM.
// A smem stride 68 (bank = 4g+c distinct), B smem stride 136 (bank = 8c+g distinct).
#define AST 68
#define BST 136
#define GSMEM_FLOATS (128 * AST + 64 * BST)   // 8704+8704 = 17408 floats = 69632 B

#define MMA_TF32(d, a, b) \
    asm volatile("mma.sync.aligned.m16n8k8.row.col.f32.tf32.tf32.f32 " \
        "{%0,%1,%2,%3}, {%4,%5,%6,%7}, {%8,%9}, {%0,%1,%2,%3};" \
        : "+f"((d)[0]), "+f"((d)[1]), "+f"((d)[2]), "+f"((d)[3]) \
        : "r"((a)[0]), "r"((a)[1]), "r"((a)[2]), "r"((a)[3]), \
          "r"((b)[0]), "r"((b)[1]))

__global__ void __launch_bounds__(256) k_gemm_mma(const float* __restrict__ A,
                                                  const float* __restrict__ W,
                                                  float* __restrict__ C, int n) {
    extern __shared__ float smem[];
    float* As = smem;              // [128][AST]  (64 k's)
    float* Bs = smem + 128 * AST;  // [64][BST]

    int tid = threadIdx.x;
    int wid = tid >> 5, lane = tid & 31;
    int gq = lane >> 2;    // 0..7
    int cq = lane & 3;     // 0..3
    int row0 = blockIdx.x << 7;

    int wm = (wid >> 2) << 6;    // 0 or 64
    int wn = (wid & 3) << 5;     // 0,32,64,96

    float acc[4][4][4];
    #pragma unroll
    for (int mt = 0; mt < 4; mt++)
        #pragma unroll
        for (int nt = 0; nt < 4; nt++)
            #pragma unroll
            for (int i = 0; i < 4; i++)
                acc[mt][nt][i] = 0.f;

    const uint32_t* Au = (const uint32_t*)As;
    const uint32_t* Bu = (const uint32_t*)Bs;

    for (int ch = 0; ch < 2; ch++) {
        int k0 = ch << 6;
        // fill A tile [128][64] (tf32-rounded)
        #pragma unroll
        for (int it = 0; it < 8; it++) {
            int t = tid + it * 256;      // 0..2047 float4 slots
            int m = t >> 4, kq = t & 15;
            int gm = row0 + m;
            float4 v = make_float4(0.f, 0.f, 0.f, 0.f);
            if (gm < n) v = *(const float4*)(A + (size_t)gm * D + k0 + kq * 4);
            v.x = to_tf32(v.x); v.y = to_tf32(v.y);
            v.z = to_tf32(v.z); v.w = to_tf32(v.w);
            *(float4*)(As + m * AST + kq * 4) = v;
        }
        // fill B tile [64][128]
        #pragma unroll
        for (int it = 0; it < 8; it++) {
            int t = tid + it * 256;
            int k = t >> 5, nq = t & 31;
            float4 v = *(const float4*)(W + (size_t)(k0 + k) * D + nq * 4);
            v.x = to_tf32(v.x); v.y = to_tf32(v.y);
            v.z = to_tf32(v.z); v.w = to_tf32(v.w);
            *(float4*)(Bs + k * BST + nq * 4) = v;
        }
        __syncthreads();

        #pragma unroll
        for (int kt = 0; kt < 8; kt++) {
            int kl = kt << 3;
            uint32_t a[4][4];
            uint32_t b[4][2];
            #pragma unroll
            for (int mt = 0; mt < 4; mt++) {
                const uint32_t* ap = Au + (wm + (mt << 4)) * AST + kl;
                a[mt][0] = ap[gq * AST + cq];
                a[mt][1] = ap[(gq + 8) * AST + cq];
                a[mt][2] = ap[gq * AST + cq + 4];
                a[mt][3] = ap[(gq + 8) * AST + cq + 4];
            }
            #pragma unroll
            for (int nt = 0; nt < 4; nt++) {
                const uint32_t* bp = Bu + kl * BST + wn + (nt << 3);
                b[nt][0] = bp[cq * BST + gq];
                b[nt][1] = bp[(cq + 4) * BST + gq];
            }
            #pragma unroll
            for (int mt = 0; mt < 4; mt++)
                #pragma unroll
                for (int nt = 0; nt < 4; nt++)
                    MMA_TF32(acc[mt][nt], a[mt], b[nt]);
        }
        __syncthreads();
    }

    #pragma unroll
    for (int mt = 0; mt < 4; mt++) {
        int r0 = row0 + wm + (mt << 4) + gq;
        int r1 = r0 + 8;
        #pragma unroll
        for (int nt = 0; nt < 4; nt++) {
            int cc = wn + (nt << 3) + (cq << 1);
            if (r0 < n)
                *(float2*)(C + (size_t)r0 * D + cc) =
                    make_float2(acc[mt][nt][0], acc[mt][nt][1]);
            if (r1 < n)
                *(float2*)(C + (size_t)r1 * D + cc) =
                    make_float2(acc[mt][nt][2], acc[mt][nt][3]);
        }
    }
}

// ---------------- aggregation ----------------
__global__ void k_agg(const float* __restrict__ h, const float* __restrict__ bias,
                      float* __restrict__ out, int n, int do_relu) {
    int gt = blockIdx.x * blockDim.x + threadIdx.x;
    int c = gt >> 5;
    int lane = gt & 31;
    if (c >= n) return;

    float dc = g_dinv[c];
    const float4* h4 = (const float4*)h;
    float4 v = h4[(size_t)c * 32 + lane];
    float s = dc * dc;
    float ax = v.x * s, ay = v.y * s, az = v.z * s, aw = v.w * s;

    int i = g_colptr[c];
    int end = g_colptr[c + 1];
    int r_next = (i < end) ? g_srow[i] : 0;
    while (i < end) {
        int r = r_next;
        int j = i + 1;
        if (j < end) r_next = g_srow[j];
        float w = g_dinv[r] * dc;
        float4 u = h4[(size_t)r * 32 + lane];
        ax += w * u.x;
        ay += w * u.y;
        az += w * u.z;
        aw += w * u.w;
        i = j;
    }

    float4 bv = ((const float4*)bias)[lane];
    ax += bv.x; ay += bv.y; az += bv.z; aw += bv.w;
    if (do_relu) {
        ax = fmaxf(ax, 0.f); ay = fmaxf(ay, 0.f);
        az = fmaxf(az, 0.f); aw = fmaxf(aw, 0.f);
    }
    ((float4*)out)[(size_t)c * 32 + lane] = make_float4(ax, ay, az, aw);
}

// ---------------- launch ----------------
extern "C" void kernel_launch(void* const* d_in, const int* in_sizes, int n_in,
                              void* d_out, int out_size) {
    const float* x  = (const float*)d_in[0];
    const int*   ei = (const int*)d_in[1];
    const float* W1 = (const float*)d_in[2];
    const float* b1 = (const float*)d_in[3];
    const float* W2 = (const float*)d_in[4];
    const float* b2 = (const float*)d_in[5];
    float* out = (float*)d_out;

    int n = in_sizes[0] / D;
    int e = in_sizes[1] / 2;
    const int* row = ei;
    const int* col = ei + e;

    void *ph = nullptr, *pz = nullptr;
    cudaGetSymbolAddress(&ph, g_h);
    cudaGetSymbolAddress(&pz, g_z);
    float* h = (float*)ph;
    float* z = (float*)pz;

    static int init_done = 0;
    static cudaStream_t s2 = nullptr;
    static cudaEvent_t ev_fork = nullptr, ev_join = nullptr;
    if (!init_done) {
        cudaFuncSetAttribute(k_gemm_mma, cudaFuncAttributeMaxDynamicSharedMemorySize,
                             GSMEM_FLOATS * 4);
        if (cudaStreamCreateWithFlags(&s2, cudaStreamNonBlocking) != cudaSuccess) s2 = nullptr;
        if (cudaEventCreateWithFlags(&ev_fork, cudaEventDisableTiming) != cudaSuccess) ev_fork = nullptr;
        if (cudaEventCreateWithFlags(&ev_join, cudaEventDisableTiming) != cudaSuccess) ev_join = nullptr;
        init_done = 1;
    }
    bool fork = (s2 && ev_fork && ev_join);
    cudaStream_t sc = fork ? s2 : (cudaStream_t)0;   // stream for CSR chain

    int nb = (n + SCAN_C - 1) / SCAN_C;
    int gemm_blocks = (n + 127) / 128;
    int agg_blocks = (n * 32 + 255) / 256;

    if (fork) {
        cudaEventRecord(ev_fork, 0);
        cudaStreamWaitEvent(s2, ev_fork, 0);
    }

    // ---- CSR build chain (side stream when forked) ----
    k_deg_init<<<(n + 255) / 256, 256, 0, sc>>>(n);
    k_deg_count<<<(e + 255) / 256, 256, 0, sc>>>(col, e);
    k_scan_partial<<<nb, SCAN_T, 0, sc>>>(n);
    k_scan_offsets<<<1, 32, 0, sc>>>(nb);
    k_scan_final<<<nb, SCAN_T, 0, sc>>>(n, e);
    k_fill<<<(e + 255) / 256, 256, 0, sc>>>(row, col, e);

    if (fork) cudaEventRecord(ev_join, s2);

    // ---- GEMM1 overlaps the CSR build ----
    k_gemm_mma<<<gemm_blocks, 256, GSMEM_FLOATS * 4>>>(x, W1, h, n);

    if (fork) cudaStreamWaitEvent((cudaStream_t)0, ev_join, 0);

    // layer 1 aggregate: z = relu(Ahat h + b1)
    k_agg<<<agg_blocks, 256>>>(h, b1, z, n, 1);
    // layer 2: h = z @ W2 ; out = Ahat h + b2
    k_gemm_mma<<<gemm_blocks, 256, GSMEM_FLOATS * 4>>>(z, W2, h, n);
    k_agg<<<agg_blocks, 256>>>(h, b2, out, n, 0);
}